// round 1
// baseline (speedup 1.0000x reference)
#include <cuda_runtime.h>
#include <cuda_fp16.h>
#include <cstdint>

// ---------------- problem constants ----------------
constexpr int KC = 128, KH = 10, KW = 4;
constexpr int H = 100, W = 64;
constexpr int NH = 10, NW = 16;            // q patch grid (100/10, 64/4)
constexpr int M = NH * NW;                 // 160 q rows
constexpr int HK = H - KH + 1;             // 91
constexpr int WK = W - KW + 1;             // 61
constexpr int NKV = HK * WK;               // 5551 kv rows
constexpr int NPAD = 5632;                 // 5551 padded to mult of 64 (88*64)
constexpr int D = KC * KH * KW;            // 5120 feature dim

// ---------------- scratch (device globals; no allocation allowed) ----------------
__device__ __half g_kv[(size_t)NPAD * D];      // 57.7 MB fp16 kv matrix
__device__ __half g_q[M * D];                  // 1.6 MB fp16 q matrix
__device__ float  g_scores[M * NPAD];          // 3.6 MB scores
__device__ __half g_attn[M * NPAD];            // 1.8 MB attn weights

// ---------------- ptx helpers ----------------
__device__ __forceinline__ uint32_t smem_u32(const void* p) {
    return (uint32_t)__cvta_generic_to_shared(p);
}
__device__ __forceinline__ void ldsm_x4(uint32_t& r0, uint32_t& r1, uint32_t& r2,
                                        uint32_t& r3, uint32_t a) {
    asm volatile("ldmatrix.sync.aligned.m8n8.x4.shared.b16 {%0,%1,%2,%3}, [%4];"
                 : "=r"(r0), "=r"(r1), "=r"(r2), "=r"(r3) : "r"(a));
}
__device__ __forceinline__ void ldsm_x4_t(uint32_t& r0, uint32_t& r1, uint32_t& r2,
                                          uint32_t& r3, uint32_t a) {
    asm volatile("ldmatrix.sync.aligned.m8n8.x4.trans.shared.b16 {%0,%1,%2,%3}, [%4];"
                 : "=r"(r0), "=r"(r1), "=r"(r2), "=r"(r3) : "r"(a));
}
__device__ __forceinline__ void mma16816(float* c, const uint32_t* a, const uint32_t* b) {
    asm volatile("mma.sync.aligned.m16n8k16.row.col.f32.f16.f16.f32 "
                 "{%0,%1,%2,%3}, {%4,%5,%6,%7}, {%8,%9}, {%0,%1,%2,%3};"
                 : "+f"(c[0]), "+f"(c[1]), "+f"(c[2]), "+f"(c[3])
                 : "r"(a[0]), "r"(a[1]), "r"(a[2]), "r"(a[3]),
                   "r"(b[0]), "r"(b[1]));
}

// ---------------- kernel 1: expand z2 -> kv fp16 [NPAD x D] ----------------
// kv[n][c*40 + i*4 + j] = z2[c][h+i][w+j],  n = h*WK + w.
// One thread handles one (n, c, i) group of 4 contiguous j's (8-byte store).
__global__ void build_kv_kernel(const float* __restrict__ z2) {
    constexpr int TOTAL = NKV * KC * KH;            // 7,105,280
    constexpr int PADG  = (NPAD - NKV) * (D / 4);   // 103,680 zero groups
    int idx = blockIdx.x * blockDim.x + threadIdx.x;
    if (idx < TOTAL) {
        int n   = idx / (KC * KH);
        int rem = idx - n * (KC * KH);
        int c   = rem / KH;
        int i   = rem - c * KH;
        int h   = n / WK;
        int w   = n - h * WK;
        const float* src = z2 + (c * H + h + i) * W + w;
        __half2 p0 = __floats2half2_rn(src[0], src[1]);
        __half2 p1 = __floats2half2_rn(src[2], src[3]);
        uint2 v;
        v.x = *reinterpret_cast<uint32_t*>(&p0);
        v.y = *reinterpret_cast<uint32_t*>(&p1);
        *reinterpret_cast<uint2*>(&g_kv[(size_t)n * D + (c * KH + i) * KW]) = v;
    } else if (idx < TOTAL + PADG) {
        int p   = idx - TOTAL;
        int pr  = p / (D / 4);
        int off = (p - pr * (D / 4)) * 4;
        *reinterpret_cast<uint2*>(&g_kv[(size_t)(NKV + pr) * D + off]) = make_uint2(0u, 0u);
    }
}

// ---------------- kernel 2: q patches -> fp16 [M x D] ----------------
__global__ void build_q_kernel(const float* __restrict__ z1) {
    constexpr int TOTAL = M * KC * KH;   // 204,800
    int idx = blockIdx.x * blockDim.x + threadIdx.x;
    if (idx >= TOTAL) return;
    int m   = idx / (KC * KH);
    int rem = idx - m * (KC * KH);
    int c   = rem / KH;
    int i   = rem - c * KH;
    int ih  = m >> 4;          // m / NW
    int iw  = m & 15;          // m % NW
    const float4 f = *reinterpret_cast<const float4*>(
        z1 + (c * H + ih * KH + i) * W + iw * KW);
    __half2 p0 = __floats2half2_rn(f.x, f.y);
    __half2 p1 = __floats2half2_rn(f.z, f.w);
    uint2 v;
    v.x = *reinterpret_cast<uint32_t*>(&p0);
    v.y = *reinterpret_cast<uint32_t*>(&p1);
    *reinterpret_cast<uint2*>(&g_q[m * D + (c * KH + i) * KW]) = v;
}

// ---------------- GEMM tiling constants ----------------
constexpr int BK  = 64;    // K chunk per stage
constexpr int BN  = 64;    // N per CTA
constexpr int LDS = 72;    // padded smem row stride (halves): 144B, conflict-free ldmatrix

// ---------------- kernel 3: scores = (q @ kv^T) / D ----------------
// CTA: full M=160 x 64 N-cols. 10 warps in 5(M) x 2(N); warp tile 32x32.
// A and B(kv) are both K-contiguous: plain ldmatrix (.row.col).
__global__ __launch_bounds__(320) void gemm_qk_kernel() {
    __shared__ __align__(16) __half As[M * LDS];    // 23.0 KB
    __shared__ __align__(16) __half Bs[BN * LDS];   //  9.2 KB
    const int n0   = blockIdx.x * BN;
    const int tid  = threadIdx.x;
    const int warp = tid >> 5, lane = tid & 31;
    const int wm = warp >> 1, wn = warp & 1;

    float acc[2][4][4] = {};

    for (int k0 = 0; k0 < D; k0 += BK) {
        __syncthreads();
        for (int t = tid; t < (M * BK / 8); t += 320) {        // 1280 int4 loads
            int r = t >> 3, c8 = (t & 7) << 3;
            *reinterpret_cast<int4*>(&As[r * LDS + c8]) =
                *reinterpret_cast<const int4*>(&g_q[r * D + k0 + c8]);
        }
        for (int t = tid; t < (BN * BK / 8); t += 320) {       // 512 int4 loads
            int r = t >> 3, c8 = (t & 7) << 3;
            *reinterpret_cast<int4*>(&Bs[r * LDS + c8]) =
                *reinterpret_cast<const int4*>(&g_kv[(size_t)(n0 + r) * D + k0 + c8]);
        }
        __syncthreads();

#pragma unroll
        for (int ks = 0; ks < BK / 16; ks++) {
            uint32_t a[2][4], b[4][2];
#pragma unroll
            for (int mi = 0; mi < 2; mi++) {
                int r = wm * 32 + mi * 16 + (lane & 15);
                int c = ks * 16 + (lane >> 4) * 8;
                ldsm_x4(a[mi][0], a[mi][1], a[mi][2], a[mi][3],
                        smem_u32(&As[r * LDS + c]));
            }
#pragma unroll
            for (int nb = 0; nb < 2; nb++) {
                int r = wn * 32 + nb * 16 + (lane & 7) + (lane >> 4) * 8;
                int c = ks * 16 + ((lane >> 3) & 1) * 8;
                uint32_t r0, r1, r2, r3;
                ldsm_x4(r0, r1, r2, r3, smem_u32(&Bs[r * LDS + c]));
                b[nb * 2][0] = r0; b[nb * 2][1] = r1;
                b[nb * 2 + 1][0] = r2; b[nb * 2 + 1][1] = r3;
            }
#pragma unroll
            for (int mi = 0; mi < 2; mi++)
#pragma unroll
                for (int ni = 0; ni < 4; ni++)
                    mma16816(acc[mi][ni], a[mi], b[ni]);
        }
    }

    const float scale = 1.0f / (float)D;
#pragma unroll
    for (int mi = 0; mi < 2; mi++)
#pragma unroll
        for (int ni = 0; ni < 4; ni++) {
            int row = wm * 32 + mi * 16 + (lane >> 2);
            int col = n0 + wn * 32 + ni * 8 + ((lane & 3) << 1);
            g_scores[row * NPAD + col]           = acc[mi][ni][0] * scale;
            g_scores[row * NPAD + col + 1]       = acc[mi][ni][1] * scale;
            g_scores[(row + 8) * NPAD + col]     = acc[mi][ni][2] * scale;
            g_scores[(row + 8) * NPAD + col + 1] = acc[mi][ni][3] * scale;
        }
}

// ---------------- kernel 4: row softmax -> attn fp16 ----------------
__global__ __launch_bounds__(256) void softmax_kernel() {
    __shared__ float row[NPAD];    // 22.5 KB: whole row resident
    __shared__ float red[256];
    const int m   = blockIdx.x;
    const int tid = threadIdx.x;

    float mx = -1e30f;
    for (int n = tid; n < NKV; n += 256) {
        float v = g_scores[m * NPAD + n];
        row[n] = v;
        mx = fmaxf(mx, v);
    }
    red[tid] = mx;
    __syncthreads();
    for (int s = 128; s > 0; s >>= 1) {
        if (tid < s) red[tid] = fmaxf(red[tid], red[tid + s]);
        __syncthreads();
    }
    const float smx = red[0];
    __syncthreads();

    float sum = 0.f;
    for (int n = tid; n < NKV; n += 256) {
        float e = __expf(row[n] - smx);
        row[n] = e;
        sum += e;
    }
    red[tid] = sum;
    __syncthreads();
    for (int s = 128; s > 0; s >>= 1) {
        if (tid < s) red[tid] += red[tid + s];
        __syncthreads();
    }
    const float inv = 1.0f / red[0];
    for (int n = tid; n < NPAD; n += 256)
        g_attn[m * NPAD + n] = (n < NKV) ? __float2half(row[n] * inv)
                                         : __float2half(0.f);
}

// ---------------- kernel 5: out = attn @ kv, remapped epilogue ----------------
// B = kv is n-contiguous here (kv[k][n]) -> ldmatrix .trans for B fragments.
__device__ __forceinline__ void store_out(float* __restrict__ out, int m, int d, float v) {
    int c   = d / 40;            // 40 = KH*KW
    int rem = d - c * 40;
    int i   = rem >> 2;
    int j   = rem & 3;
    int ih  = m >> 4;
    int iw  = m & 15;
    out[(c * H + ih * KH + i) * W + iw * KW + j] = v;
}

__global__ __launch_bounds__(320) void gemm_av_kernel(float* __restrict__ out) {
    __shared__ __align__(16) __half As[M * LDS];    // attn tile 160 x 64
    __shared__ __align__(16) __half Bs[BK * LDS];   // kv tile   64 x 64 (k-major rows)
    const int n0   = blockIdx.x * BN;               // over D = 5120
    const int tid  = threadIdx.x;
    const int warp = tid >> 5, lane = tid & 31;
    const int wm = warp >> 1, wn = warp & 1;

    float acc[2][4][4] = {};

    for (int k0 = 0; k0 < NPAD; k0 += BK) {
        __syncthreads();
        for (int t = tid; t < (M * BK / 8); t += 320) {
            int r = t >> 3, c8 = (t & 7) << 3;
            *reinterpret_cast<int4*>(&As[r * LDS + c8]) =
                *reinterpret_cast<const int4*>(&g_attn[r * NPAD + k0 + c8]);
        }
        for (int t = tid; t < (BK * BN / 8); t += 320) {
            int r = t >> 3, c8 = (t & 7) << 3;
            *reinterpret_cast<int4*>(&Bs[r * LDS + c8]) =
                *reinterpret_cast<const int4*>(&g_kv[(size_t)(k0 + r) * D + n0 + c8]);
        }
        __syncthreads();

#pragma unroll
        for (int ks = 0; ks < BK / 16; ks++) {
            uint32_t a[2][4], b[4][2];
#pragma unroll
            for (int mi = 0; mi < 2; mi++) {
                int r = wm * 32 + mi * 16 + (lane & 15);
                int c = ks * 16 + (lane >> 4) * 8;
                ldsm_x4(a[mi][0], a[mi][1], a[mi][2], a[mi][3],
                        smem_u32(&As[r * LDS + c]));
            }
#pragma unroll
            for (int nb = 0; nb < 2; nb++) {
                int r = ks * 16 + (lane & 7) + ((lane >> 3) & 1) * 8;
                int c = wn * 32 + nb * 16 + (lane >> 4) * 8;
                uint32_t r0, r1, r2, r3;
                ldsm_x4_t(r0, r1, r2, r3, smem_u32(&Bs[r * LDS + c]));
                b[nb * 2][0] = r0; b[nb * 2][1] = r1;
                b[nb * 2 + 1][0] = r2; b[nb * 2 + 1][1] = r3;
            }
#pragma unroll
            for (int mi = 0; mi < 2; mi++)
#pragma unroll
                for (int ni = 0; ni < 4; ni++)
                    mma16816(acc[mi][ni], a[mi], b[ni]);
        }
    }

#pragma unroll
    for (int mi = 0; mi < 2; mi++)
#pragma unroll
        for (int ni = 0; ni < 4; ni++) {
            int row = wm * 32 + mi * 16 + (lane >> 2);
            int col = n0 + wn * 32 + ni * 8 + ((lane & 3) << 1);
            store_out(out, row,     col,     acc[mi][ni][0]);
            store_out(out, row,     col + 1, acc[mi][ni][1]);
            store_out(out, row + 8, col,     acc[mi][ni][2]);
            store_out(out, row + 8, col + 1, acc[mi][ni][3]);
        }
}

// ---------------- launch ----------------
extern "C" void kernel_launch(void* const* d_in, const int* in_sizes, int n_in,
                              void* d_out, int out_size) {
    const float* z1 = (const float*)d_in[0];   // z1_hat (1,128,100,64) f32
    const float* z2 = (const float*)d_in[1];   // z2     (1,128,100,64) f32
    float* out = (float*)d_out;                // (1,128,100,64) f32

    build_q_kernel<<<800, 256>>>(z1);
    build_kv_kernel<<<28160, 256>>>(z2);       // 7,208,960 work items (incl. padding)
    gemm_qk_kernel<<<NPAD / BN, 320>>>();      // 88 CTAs
    softmax_kernel<<<M, 256>>>();              // 160 CTAs
    gemm_av_kernel<<<D / BN, 320>>>(out);      // 80 CTAs
}

// round 2
// speedup vs baseline: 1.2802x; 1.2802x over previous
#include <cuda_runtime.h>
#include <cuda_fp16.h>
#include <cstdint>

// ---------------- problem constants ----------------
constexpr int KC = 128, KH = 10, KW = 4;
constexpr int H = 100, W = 64;
constexpr int NH = 10, NW = 16;            // q patch grid
constexpr int M = NH * NW;                 // 160 q rows
constexpr int HK = H - KH + 1;             // 91
constexpr int WK = W - KW + 1;             // 61
constexpr int NKV = HK * WK;               // 5551 kv rows
constexpr int NPAD = 5632;                 // padded to 88*64
constexpr int D = KC * KH * KW;            // 5120

// ---------------- scratch ----------------
__device__ __half g_kv[(size_t)NPAD * D];
__device__ __half g_q[M * D];
__device__ float  g_scores[M * NPAD];
__device__ __half g_attn[M * NPAD];

// ---------------- ptx helpers ----------------
__device__ __forceinline__ uint32_t smem_u32(const void* p) {
    return (uint32_t)__cvta_generic_to_shared(p);
}
__device__ __forceinline__ void ldsm_x4(uint32_t& r0, uint32_t& r1, uint32_t& r2,
                                        uint32_t& r3, uint32_t a) {
    asm volatile("ldmatrix.sync.aligned.m8n8.x4.shared.b16 {%0,%1,%2,%3}, [%4];"
                 : "=r"(r0), "=r"(r1), "=r"(r2), "=r"(r3) : "r"(a));
}
__device__ __forceinline__ void ldsm_x4_t(uint32_t& r0, uint32_t& r1, uint32_t& r2,
                                          uint32_t& r3, uint32_t a) {
    asm volatile("ldmatrix.sync.aligned.m8n8.x4.trans.shared.b16 {%0,%1,%2,%3}, [%4];"
                 : "=r"(r0), "=r"(r1), "=r"(r2), "=r"(r3) : "r"(a));
}
__device__ __forceinline__ void mma16816(float* c, const uint32_t* a, const uint32_t* b) {
    asm volatile("mma.sync.aligned.m16n8k16.row.col.f32.f16.f16.f32 "
                 "{%0,%1,%2,%3}, {%4,%5,%6,%7}, {%8,%9}, {%0,%1,%2,%3};"
                 : "+f"(c[0]), "+f"(c[1]), "+f"(c[2]), "+f"(c[3])
                 : "r"(a[0]), "r"(a[1]), "r"(a[2]), "r"(a[3]),
                   "r"(b[0]), "r"(b[1]));
}
__device__ __forceinline__ void cpasync16(uint32_t s, const void* g) {
    asm volatile("cp.async.cg.shared.global [%0], [%1], 16;" :: "r"(s), "l"(g));
}
#define CP_COMMIT() asm volatile("cp.async.commit_group;")
#define CP_WAIT(n)  asm volatile("cp.async.wait_group %0;" :: "n"(n))

// ---------------- kernel 1: expand z2 -> kv fp16 ----------------
__global__ void build_kv_kernel(const float* __restrict__ z2) {
    constexpr int TOTAL = NKV * KC * KH;
    constexpr int PADG  = (NPAD - NKV) * (D / 4);
    int idx = blockIdx.x * blockDim.x + threadIdx.x;
    if (idx < TOTAL) {
        int n   = idx / (KC * KH);
        int rem = idx - n * (KC * KH);
        int c   = rem / KH;
        int i   = rem - c * KH;
        int h   = n / WK;
        int w   = n - h * WK;
        const float* src = z2 + (c * H + h + i) * W + w;
        __half2 p0 = __floats2half2_rn(src[0], src[1]);
        __half2 p1 = __floats2half2_rn(src[2], src[3]);
        uint2 v;
        v.x = *reinterpret_cast<uint32_t*>(&p0);
        v.y = *reinterpret_cast<uint32_t*>(&p1);
        *reinterpret_cast<uint2*>(&g_kv[(size_t)n * D + (c * KH + i) * KW]) = v;
    } else if (idx < TOTAL + PADG) {
        int p   = idx - TOTAL;
        int pr  = p / (D / 4);
        int off = (p - pr * (D / 4)) * 4;
        *reinterpret_cast<uint2*>(&g_kv[(size_t)(NKV + pr) * D + off]) = make_uint2(0u, 0u);
    }
}

// ---------------- kernel 2: q patches -> fp16 ----------------
__global__ void build_q_kernel(const float* __restrict__ z1) {
    constexpr int TOTAL = M * KC * KH;
    int idx = blockIdx.x * blockDim.x + threadIdx.x;
    if (idx >= TOTAL) return;
    int m   = idx / (KC * KH);
    int rem = idx - m * (KC * KH);
    int c   = rem / KH;
    int i   = rem - c * KH;
    int ih  = m >> 4;
    int iw  = m & 15;
    const float4 f = *reinterpret_cast<const float4*>(
        z1 + (c * H + ih * KH + i) * W + iw * KW);
    __half2 p0 = __floats2half2_rn(f.x, f.y);
    __half2 p1 = __floats2half2_rn(f.z, f.w);
    uint2 v;
    v.x = *reinterpret_cast<uint32_t*>(&p0);
    v.y = *reinterpret_cast<uint32_t*>(&p1);
    *reinterpret_cast<uint2*>(&g_q[m * D + (c * KH + i) * KW]) = v;
}

// ---------------- GEMM tiling ----------------
constexpr int BK  = 64;
constexpr int BN  = 64;
constexpr int LDS = 72;                          // padded smem row stride (halves)
constexpr int STAGES = 4;
constexpr int A_HALVES = M * LDS;                // 11520
constexpr int B_HALVES = BN * LDS;               // 4608
constexpr int STAGE_HALVES = A_HALVES + B_HALVES;
constexpr int SMEM_BYTES = STAGES * STAGE_HALVES * 2;   // 129024

// ---------------- kernel 3: scores = (q @ kv^T) / D ----------------
__global__ __launch_bounds__(320) void gemm_qk_kernel() {
    extern __shared__ __align__(16) __half sm[];
    const int n0   = blockIdx.x * BN;
    const int tid  = threadIdx.x;
    const int warp = tid >> 5, lane = tid & 31;
    const int wm = warp >> 1, wn = warp & 1;
    constexpr int KT = D / BK;                   // 80

    auto load_stage = [&](int s, int kt) {
        const int k0 = kt * BK;
        __half* As = sm + s * STAGE_HALVES;
        __half* Bs = As + A_HALVES;
#pragma unroll
        for (int i = 0; i < 4; i++) {            // 1280 A copies / 320 thr
            int t = tid + i * 320;
            int r = t >> 3, c8 = (t & 7) << 3;
            cpasync16(smem_u32(&As[r * LDS + c8]), &g_q[r * D + k0 + c8]);
        }
        for (int t = tid; t < 512; t += 320) {   // 512 B copies
            int r = t >> 3, c8 = (t & 7) << 3;
            cpasync16(smem_u32(&Bs[r * LDS + c8]),
                      &g_kv[(size_t)(n0 + r) * D + k0 + c8]);
        }
    };

#pragma unroll
    for (int s = 0; s < STAGES - 1; s++) { load_stage(s, s); CP_COMMIT(); }

    float acc[2][4][4] = {};

    for (int kt = 0; kt < KT; kt++) {
        CP_WAIT(STAGES - 2);
        __syncthreads();
        int nxt = kt + STAGES - 1;
        if (nxt < KT) load_stage(nxt & (STAGES - 1), nxt);
        CP_COMMIT();

        const __half* As = sm + (kt & (STAGES - 1)) * STAGE_HALVES;
        const __half* Bs = As + A_HALVES;
#pragma unroll
        for (int ks = 0; ks < BK / 16; ks++) {
            uint32_t a[2][4], b[4][2];
#pragma unroll
            for (int mi = 0; mi < 2; mi++) {
                int r = wm * 32 + mi * 16 + (lane & 15);
                int c = ks * 16 + (lane >> 4) * 8;
                ldsm_x4(a[mi][0], a[mi][1], a[mi][2], a[mi][3],
                        smem_u32(&As[r * LDS + c]));
            }
#pragma unroll
            for (int nb = 0; nb < 2; nb++) {
                int r = wn * 32 + nb * 16 + (lane & 7) + (lane >> 4) * 8;
                int c = ks * 16 + ((lane >> 3) & 1) * 8;
                uint32_t r0, r1, r2, r3;
                ldsm_x4(r0, r1, r2, r3, smem_u32(&Bs[r * LDS + c]));
                b[nb * 2][0] = r0; b[nb * 2][1] = r1;
                b[nb * 2 + 1][0] = r2; b[nb * 2 + 1][1] = r3;
            }
#pragma unroll
            for (int mi = 0; mi < 2; mi++)
#pragma unroll
                for (int ni = 0; ni < 4; ni++)
                    mma16816(acc[mi][ni], a[mi], b[ni]);
        }
    }

    const float scale = 1.0f / (float)D;
#pragma unroll
    for (int mi = 0; mi < 2; mi++)
#pragma unroll
        for (int ni = 0; ni < 4; ni++) {
            int row = wm * 32 + mi * 16 + (lane >> 2);
            int col = n0 + wn * 32 + ni * 8 + ((lane & 3) << 1);
            g_scores[row * NPAD + col]           = acc[mi][ni][0] * scale;
            g_scores[row * NPAD + col + 1]       = acc[mi][ni][1] * scale;
            g_scores[(row + 8) * NPAD + col]     = acc[mi][ni][2] * scale;
            g_scores[(row + 8) * NPAD + col + 1] = acc[mi][ni][3] * scale;
        }
}

// ---------------- kernel 4: row softmax ----------------
__global__ __launch_bounds__(256) void softmax_kernel() {
    __shared__ float row[NPAD];
    __shared__ float red[256];
    const int m   = blockIdx.x;
    const int tid = threadIdx.x;

    float mx = -1e30f;
    for (int n = tid; n < NKV; n += 256) {
        float v = g_scores[m * NPAD + n];
        row[n] = v;
        mx = fmaxf(mx, v);
    }
    red[tid] = mx;
    __syncthreads();
    for (int s = 128; s > 0; s >>= 1) {
        if (tid < s) red[tid] = fmaxf(red[tid], red[tid + s]);
        __syncthreads();
    }
    const float smx = red[0];
    __syncthreads();

    float sum = 0.f;
    for (int n = tid; n < NKV; n += 256) {
        float e = __expf(row[n] - smx);
        row[n] = e;
        sum += e;
    }
    red[tid] = sum;
    __syncthreads();
    for (int s = 128; s > 0; s >>= 1) {
        if (tid < s) red[tid] += red[tid + s];
        __syncthreads();
    }
    const float inv = 1.0f / red[0];
    for (int n = tid; n < NPAD; n += 256)
        g_attn[m * NPAD + n] = (n < NKV) ? __float2half(row[n] * inv)
                                         : __float2half(0.f);
}

// ---------------- kernel 5: out = attn @ kv ----------------
__device__ __forceinline__ void store_out(float* __restrict__ out, int m, int d, float v) {
    int c   = d / 40;
    int rem = d - c * 40;
    int i   = rem >> 2;
    int j   = rem & 3;
    int ih  = m >> 4;
    int iw  = m & 15;
    out[(c * H + ih * KH + i) * W + iw * KW + j] = v;
}

__global__ __launch_bounds__(320) void gemm_av_kernel(float* __restrict__ out) {
    extern __shared__ __align__(16) __half sm[];
    const int n0   = blockIdx.x * BN;            // over D
    const int tid  = threadIdx.x;
    const int warp = tid >> 5, lane = tid & 31;
    const int wm = warp >> 1, wn = warp & 1;
    constexpr int KT = NPAD / BK;                // 88

    auto load_stage = [&](int s, int kt) {
        const int k0 = kt * BK;
        __half* As = sm + s * STAGE_HALVES;
        __half* Bs = As + A_HALVES;
#pragma unroll
        for (int i = 0; i < 4; i++) {
            int t = tid + i * 320;
            int r = t >> 3, c8 = (t & 7) << 3;
            cpasync16(smem_u32(&As[r * LDS + c8]), &g_attn[r * NPAD + k0 + c8]);
        }
        for (int t = tid; t < 512; t += 320) {
            int r = t >> 3, c8 = (t & 7) << 3;
            cpasync16(smem_u32(&Bs[r * LDS + c8]),
                      &g_kv[(size_t)(k0 + r) * D + n0 + c8]);
        }
    };

#pragma unroll
    for (int s = 0; s < STAGES - 1; s++) { load_stage(s, s); CP_COMMIT(); }

    float acc[2][4][4] = {};

    for (int kt = 0; kt < KT; kt++) {
        CP_WAIT(STAGES - 2);
        __syncthreads();
        int nxt = kt + STAGES - 1;
        if (nxt < KT) load_stage(nxt & (STAGES - 1), nxt);
        CP_COMMIT();

        const __half* As = sm + (kt & (STAGES - 1)) * STAGE_HALVES;
        const __half* Bs = As + A_HALVES;
#pragma unroll
        for (int ks = 0; ks < BK / 16; ks++) {
            uint32_t a[2][4], b[4][2];
#pragma unroll
            for (int mi = 0; mi < 2; mi++) {
                int r = wm * 32 + mi * 16 + (lane & 15);
                int c = ks * 16 + (lane >> 4) * 8;
                ldsm_x4(a[mi][0], a[mi][1], a[mi][2], a[mi][3],
                        smem_u32(&As[r * LDS + c]));
            }
#pragma unroll
            for (int nb = 0; nb < 2; nb++) {
                int r = ks * 16 + (lane & 7) + ((lane >> 3) & 1) * 8;
                int c = wn * 32 + nb * 16 + (lane >> 4) * 8;
                uint32_t r0, r1, r2, r3;
                ldsm_x4_t(r0, r1, r2, r3, smem_u32(&Bs[r * LDS + c]));
                b[nb * 2][0] = r0; b[nb * 2][1] = r1;
                b[nb * 2 + 1][0] = r2; b[nb * 2 + 1][1] = r3;
            }
#pragma unroll
            for (int mi = 0; mi < 2; mi++)
#pragma unroll
                for (int ni = 0; ni < 4; ni++)
                    mma16816(acc[mi][ni], a[mi], b[ni]);
        }
    }

#pragma unroll
    for (int mi = 0; mi < 2; mi++)
#pragma unroll
        for (int ni = 0; ni < 4; ni++) {
            int row = wm * 32 + mi * 16 + (lane >> 2);
            int col = n0 + wn * 32 + ni * 8 + ((lane & 3) << 1);
            store_out(out, row,     col,     acc[mi][ni][0]);
            store_out(out, row,     col + 1, acc[mi][ni][1]);
            store_out(out, row + 8, col,     acc[mi][ni][2]);
            store_out(out, row + 8, col + 1, acc[mi][ni][3]);
        }
}

// ---------------- launch ----------------
extern "C" void kernel_launch(void* const* d_in, const int* in_sizes, int n_in,
                              void* d_out, int out_size) {
    const float* z1 = (const float*)d_in[0];
    const float* z2 = (const float*)d_in[1];
    float* out = (float*)d_out;

    cudaFuncSetAttribute(gemm_qk_kernel,
                         cudaFuncAttributeMaxDynamicSharedMemorySize, SMEM_BYTES);
    cudaFuncSetAttribute(gemm_av_kernel,
                         cudaFuncAttributeMaxDynamicSharedMemorySize, SMEM_BYTES);

    build_q_kernel<<<800, 256>>>(z1);
    build_kv_kernel<<<28160, 256>>>(z2);
    gemm_qk_kernel<<<NPAD / BN, 320, SMEM_BYTES>>>();
    softmax_kernel<<<M, 256>>>();
    gemm_av_kernel<<<D / BN, 320, SMEM_BYTES>>>(out);
}

// round 3
// speedup vs baseline: 2.4445x; 1.9094x over previous
#include <cuda_runtime.h>
#include <cuda_fp16.h>
#include <cstdint>

// ---------------- problem constants ----------------
constexpr int KC = 128, KH = 10, KW = 4;
constexpr int H = 100, W = 64;
constexpr int NH = 10, NW = 16;
constexpr int M = NH * NW;                 // 160 q rows
constexpr int MPAD = 192;                  // padded to 3*64
constexpr int HK = H - KH + 1;             // 91
constexpr int WK = W - KW + 1;             // 61
constexpr int NKV = HK * WK;               // 5551
constexpr int NPAD = 5632;                 // 88*64
constexpr int D = KC * KH * KW;            // 5120

// ---------------- scratch ----------------
__device__ __half g_kv[(size_t)NPAD * D];
__device__ __half g_q[MPAD * D];               // rows 160..191 stay zero (static init)
__device__ float  g_scores[MPAD * NPAD];
__device__ __half g_attn[MPAD * NPAD];         // rows 160..191 stay zero

// ---------------- ptx helpers ----------------
__device__ __forceinline__ uint32_t smem_u32(const void* p) {
    return (uint32_t)__cvta_generic_to_shared(p);
}
__device__ __forceinline__ void ldsm_x4(uint32_t& r0, uint32_t& r1, uint32_t& r2,
                                        uint32_t& r3, uint32_t a) {
    asm volatile("ldmatrix.sync.aligned.m8n8.x4.shared.b16 {%0,%1,%2,%3}, [%4];"
                 : "=r"(r0), "=r"(r1), "=r"(r2), "=r"(r3) : "r"(a));
}
__device__ __forceinline__ void ldsm_x4_t(uint32_t& r0, uint32_t& r1, uint32_t& r2,
                                          uint32_t& r3, uint32_t a) {
    asm volatile("ldmatrix.sync.aligned.m8n8.x4.trans.shared.b16 {%0,%1,%2,%3}, [%4];"
                 : "=r"(r0), "=r"(r1), "=r"(r2), "=r"(r3) : "r"(a));
}
__device__ __forceinline__ void mma16816(float* c, const uint32_t* a, const uint32_t* b) {
    asm volatile("mma.sync.aligned.m16n8k16.row.col.f32.f16.f16.f32 "
                 "{%0,%1,%2,%3}, {%4,%5,%6,%7}, {%8,%9}, {%0,%1,%2,%3};"
                 : "+f"(c[0]), "+f"(c[1]), "+f"(c[2]), "+f"(c[3])
                 : "r"(a[0]), "r"(a[1]), "r"(a[2]), "r"(a[3]),
                   "r"(b[0]), "r"(b[1]));
}
__device__ __forceinline__ void cpasync16(uint32_t s, const void* g) {
    asm volatile("cp.async.cg.shared.global [%0], [%1], 16;" :: "r"(s), "l"(g));
}
#define CP_COMMIT() asm volatile("cp.async.commit_group;")
#define CP_WAIT(n)  asm volatile("cp.async.wait_group %0;" :: "n"(n))

// ---------------- kernel 1: expand z2 -> kv fp16 ----------------
__global__ void build_kv_kernel(const float* __restrict__ z2) {
    constexpr int TOTAL = NKV * KC * KH;
    constexpr int PADG  = (NPAD - NKV) * (D / 4);
    int idx = blockIdx.x * blockDim.x + threadIdx.x;
    if (idx < TOTAL) {
        int n   = idx / (KC * KH);
        int rem = idx - n * (KC * KH);
        int c   = rem / KH;
        int i   = rem - c * KH;
        int h   = n / WK;
        int w   = n - h * WK;
        const float* src = z2 + (c * H + h + i) * W + w;
        __half2 p0 = __floats2half2_rn(src[0], src[1]);
        __half2 p1 = __floats2half2_rn(src[2], src[3]);
        uint2 v;
        v.x = *reinterpret_cast<uint32_t*>(&p0);
        v.y = *reinterpret_cast<uint32_t*>(&p1);
        *reinterpret_cast<uint2*>(&g_kv[(size_t)n * D + (c * KH + i) * KW]) = v;
    } else if (idx < TOTAL + PADG) {
        int p   = idx - TOTAL;
        int pr  = p / (D / 4);
        int off = (p - pr * (D / 4)) * 4;
        *reinterpret_cast<uint2*>(&g_kv[(size_t)(NKV + pr) * D + off]) = make_uint2(0u, 0u);
    }
}

// ---------------- kernel 2: q patches -> fp16 ----------------
__global__ void build_q_kernel(const float* __restrict__ z1) {
    constexpr int TOTAL = M * KC * KH;
    int idx = blockIdx.x * blockDim.x + threadIdx.x;
    if (idx >= TOTAL) return;
    int m   = idx / (KC * KH);
    int rem = idx - m * (KC * KH);
    int c   = rem / KH;
    int i   = rem - c * KH;
    int ih  = m >> 4;
    int iw  = m & 15;
    const float4 f = *reinterpret_cast<const float4*>(
        z1 + (c * H + ih * KH + i) * W + iw * KW);
    __half2 p0 = __floats2half2_rn(f.x, f.y);
    __half2 p1 = __floats2half2_rn(f.z, f.w);
    uint2 v;
    v.x = *reinterpret_cast<uint32_t*>(&p0);
    v.y = *reinterpret_cast<uint32_t*>(&p1);
    *reinterpret_cast<uint2*>(&g_q[m * D + (c * KH + i) * KW]) = v;
}

// ---------------- GEMM tiling: 64x64 CTA, 128 threads, 2x2 warps ----------------
constexpr int BM  = 64;
constexpr int BK  = 64;
constexpr int BN  = 64;
constexpr int LDS = 72;
constexpr int STAGES = 4;
constexpr int A_HALVES = BM * LDS;               // 4608
constexpr int B_HALVES = BN * LDS;               // 4608
constexpr int STAGE_HALVES = A_HALVES + B_HALVES;
constexpr int SMEM_BYTES = STAGES * STAGE_HALVES * 2;   // 73728

// ---------------- kernel 3: scores = (q @ kv^T) / D ----------------
__global__ __launch_bounds__(128, 3) void gemm_qk_kernel() {
    extern __shared__ __align__(16) __half sm[];
    const int n0   = blockIdx.x * BN;
    const int m0   = blockIdx.y * BM;
    const int tid  = threadIdx.x;
    const int warp = tid >> 5, lane = tid & 31;
    const int wm = warp >> 1, wn = warp & 1;
    constexpr int KT = D / BK;                   // 80

    auto load_stage = [&](int s, int kt) {
        const int k0 = kt * BK;
        __half* As = sm + s * STAGE_HALVES;
        __half* Bs = As + A_HALVES;
#pragma unroll
        for (int i = 0; i < 4; i++) {            // 512 A copies / 128 thr
            int t = tid + i * 128;
            int r = t >> 3, c8 = (t & 7) << 3;
            cpasync16(smem_u32(&As[r * LDS + c8]),
                      &g_q[(m0 + r) * D + k0 + c8]);
        }
#pragma unroll
        for (int i = 0; i < 4; i++) {            // 512 B copies
            int t = tid + i * 128;
            int r = t >> 3, c8 = (t & 7) << 3;
            cpasync16(smem_u32(&Bs[r * LDS + c8]),
                      &g_kv[(size_t)(n0 + r) * D + k0 + c8]);
        }
    };

#pragma unroll
    for (int s = 0; s < STAGES - 1; s++) { load_stage(s, s); CP_COMMIT(); }

    float acc[2][4][4] = {};

    for (int kt = 0; kt < KT; kt++) {
        CP_WAIT(STAGES - 2);
        __syncthreads();
        int nxt = kt + STAGES - 1;
        if (nxt < KT) load_stage(nxt & (STAGES - 1), nxt);
        CP_COMMIT();

        const __half* As = sm + (kt & (STAGES - 1)) * STAGE_HALVES;
        const __half* Bs = As + A_HALVES;
#pragma unroll
        for (int ks = 0; ks < BK / 16; ks++) {
            uint32_t a[2][4], b[4][2];
#pragma unroll
            for (int mi = 0; mi < 2; mi++) {
                int r = wm * 32 + mi * 16 + (lane & 15);
                int c = ks * 16 + (lane >> 4) * 8;
                ldsm_x4(a[mi][0], a[mi][1], a[mi][2], a[mi][3],
                        smem_u32(&As[r * LDS + c]));
            }
#pragma unroll
            for (int nb = 0; nb < 2; nb++) {
                int r = wn * 32 + nb * 16 + (lane & 7) + (lane >> 4) * 8;
                int c = ks * 16 + ((lane >> 3) & 1) * 8;
                uint32_t r0, r1, r2, r3;
                ldsm_x4(r0, r1, r2, r3, smem_u32(&Bs[r * LDS + c]));
                b[nb * 2][0] = r0; b[nb * 2][1] = r1;
                b[nb * 2 + 1][0] = r2; b[nb * 2 + 1][1] = r3;
            }
#pragma unroll
            for (int mi = 0; mi < 2; mi++)
#pragma unroll
                for (int ni = 0; ni < 4; ni++)
                    mma16816(acc[mi][ni], a[mi], b[ni]);
        }
    }

    const float scale = 1.0f / (float)D;
#pragma unroll
    for (int mi = 0; mi < 2; mi++)
#pragma unroll
        for (int ni = 0; ni < 4; ni++) {
            int row = m0 + wm * 32 + mi * 16 + (lane >> 2);
            int col = n0 + wn * 32 + ni * 8 + ((lane & 3) << 1);
            g_scores[row * NPAD + col]           = acc[mi][ni][0] * scale;
            g_scores[row * NPAD + col + 1]       = acc[mi][ni][1] * scale;
            g_scores[(row + 8) * NPAD + col]     = acc[mi][ni][2] * scale;
            g_scores[(row + 8) * NPAD + col + 1] = acc[mi][ni][3] * scale;
        }
}

// ---------------- kernel 4: row softmax ----------------
__global__ __launch_bounds__(512) void softmax_kernel() {
    __shared__ float row[NPAD];
    __shared__ float red[512];
    const int m   = blockIdx.x;
    const int tid = threadIdx.x;

    float mx = -1e30f;
    for (int n = tid; n < NKV; n += 512) {
        float v = g_scores[m * NPAD + n];
        row[n] = v;
        mx = fmaxf(mx, v);
    }
    red[tid] = mx;
    __syncthreads();
    for (int s = 256; s > 0; s >>= 1) {
        if (tid < s) red[tid] = fmaxf(red[tid], red[tid + s]);
        __syncthreads();
    }
    const float smx = red[0];
    __syncthreads();

    float sum = 0.f;
    for (int n = tid; n < NKV; n += 512) {
        float e = __expf(row[n] - smx);
        row[n] = e;
        sum += e;
    }
    red[tid] = sum;
    __syncthreads();
    for (int s = 256; s > 0; s >>= 1) {
        if (tid < s) red[tid] += red[tid + s];
        __syncthreads();
    }
    const float inv = 1.0f / red[0];
    for (int n = tid; n < NPAD; n += 512)
        g_attn[m * NPAD + n] = (n < NKV) ? __float2half(row[n] * inv)
                                         : __float2half(0.f);
}

// ---------------- kernel 5: out = attn @ kv ----------------
__device__ __forceinline__ void store_out(float* __restrict__ out, int m, int d, float v) {
    if (m >= M) return;
    int c   = d / 40;
    int rem = d - c * 40;
    int i   = rem >> 2;
    int j   = rem & 3;
    int ih  = m >> 4;
    int iw  = m & 15;
    out[(c * H + ih * KH + i) * W + iw * KW + j] = v;
}

__global__ __launch_bounds__(128, 3) void gemm_av_kernel(float* __restrict__ out) {
    extern __shared__ __align__(16) __half sm[];
    const int n0   = blockIdx.x * BN;            // over D
    const int m0   = blockIdx.y * BM;
    const int tid  = threadIdx.x;
    const int warp = tid >> 5, lane = tid & 31;
    const int wm = warp >> 1, wn = warp & 1;
    constexpr int KT = NPAD / BK;                // 88

    auto load_stage = [&](int s, int kt) {
        const int k0 = kt * BK;
        __half* As = sm + s * STAGE_HALVES;
        __half* Bs = As + A_HALVES;
#pragma unroll
        for (int i = 0; i < 4; i++) {
            int t = tid + i * 128;
            int r = t >> 3, c8 = (t & 7) << 3;
            cpasync16(smem_u32(&As[r * LDS + c8]),
                      &g_attn[(m0 + r) * NPAD + k0 + c8]);
        }
#pragma unroll
        for (int i = 0; i < 4; i++) {
            int t = tid + i * 128;
            int r = t >> 3, c8 = (t & 7) << 3;
            cpasync16(smem_u32(&Bs[r * LDS + c8]),
                      &g_kv[(size_t)(k0 + r) * D + n0 + c8]);
        }
    };

#pragma unroll
    for (int s = 0; s < STAGES - 1; s++) { load_stage(s, s); CP_COMMIT(); }

    float acc[2][4][4] = {};

    for (int kt = 0; kt < KT; kt++) {
        CP_WAIT(STAGES - 2);
        __syncthreads();
        int nxt = kt + STAGES - 1;
        if (nxt < KT) load_stage(nxt & (STAGES - 1), nxt);
        CP_COMMIT();

        const __half* As = sm + (kt & (STAGES - 1)) * STAGE_HALVES;
        const __half* Bs = As + A_HALVES;
#pragma unroll
        for (int ks = 0; ks < BK / 16; ks++) {
            uint32_t a[2][4], b[4][2];
#pragma unroll
            for (int mi = 0; mi < 2; mi++) {
                int r = wm * 32 + mi * 16 + (lane & 15);
                int c = ks * 16 + (lane >> 4) * 8;
                ldsm_x4(a[mi][0], a[mi][1], a[mi][2], a[mi][3],
                        smem_u32(&As[r * LDS + c]));
            }
#pragma unroll
            for (int nb = 0; nb < 2; nb++) {
                int r = ks * 16 + (lane & 7) + ((lane >> 3) & 1) * 8;
                int c = wn * 32 + nb * 16 + (lane >> 4) * 8;
                uint32_t r0, r1, r2, r3;
                ldsm_x4_t(r0, r1, r2, r3, smem_u32(&Bs[r * LDS + c]));
                b[nb * 2][0] = r0; b[nb * 2][1] = r1;
                b[nb * 2 + 1][0] = r2; b[nb * 2 + 1][1] = r3;
            }
#pragma unroll
            for (int mi = 0; mi < 2; mi++)
#pragma unroll
                for (int ni = 0; ni < 4; ni++)
                    mma16816(acc[mi][ni], a[mi], b[ni]);
        }
    }

#pragma unroll
    for (int mi = 0; mi < 2; mi++)
#pragma unroll
        for (int ni = 0; ni < 4; ni++) {
            int row = m0 + wm * 32 + mi * 16 + (lane >> 2);
            int col = n0 + wn * 32 + ni * 8 + ((lane & 3) << 1);
            store_out(out, row,     col,     acc[mi][ni][0]);
            store_out(out, row,     col + 1, acc[mi][ni][1]);
            store_out(out, row + 8, col,     acc[mi][ni][2]);
            store_out(out, row + 8, col + 1, acc[mi][ni][3]);
        }
}

// ---------------- launch ----------------
extern "C" void kernel_launch(void* const* d_in, const int* in_sizes, int n_in,
                              void* d_out, int out_size) {
    const float* z1 = (const float*)d_in[0];
    const float* z2 = (const float*)d_in[1];
    float* out = (float*)d_out;

    cudaFuncSetAttribute(gemm_qk_kernel,
                         cudaFuncAttributeMaxDynamicSharedMemorySize, SMEM_BYTES);
    cudaFuncSetAttribute(gemm_av_kernel,
                         cudaFuncAttributeMaxDynamicSharedMemorySize, SMEM_BYTES);

    build_q_kernel<<<800, 256>>>(z1);
    build_kv_kernel<<<28160, 256>>>(z2);
    gemm_qk_kernel<<<dim3(NPAD / BN, MPAD / BM), 128, SMEM_BYTES>>>();   // 88x3 = 264 CTAs
    softmax_kernel<<<M, 512>>>();
    gemm_av_kernel<<<dim3(D / BN, MPAD / BM), 128, SMEM_BYTES>>>(out);   // 80x3 = 240 CTAs
}